// round 14
// baseline (speedup 1.0000x reference)
#include <cuda_runtime.h>
#include <cuda_fp16.h>
#include <stdint.h>

#define N_NODES 50000
#define N_EDGES 800000
#define IN_CH 384
#define HID 128

#define SCAN_BLK 256
#define SCAN_NBLK ((N_NODES + SCAN_BLK - 1) / SCAN_BLK)   // 196

// ---------------- scratch (device-code-only references!) ----------------
__device__ __align__(256) __half g_h1[N_NODES * HID];    // GEMM1 out (fp16)
__device__ __align__(256) __half g_h2[N_NODES * HID];    // layer-1 out (fp16)
__device__ __align__(256) __half g_agg2[N_NODES * HID];  // A_hat*h2 (fp16)
__device__ float g_dinv[N_NODES];
__device__ int g_degi[N_NODES];
__device__ int g_rowptr[N_NODES + 1];
__device__ int g_cursor[N_NODES];
__device__ int g_col[N_EDGES];
__device__ int g_bsum[SCAN_NBLK];

// ---------------- degree ----------------
__global__ void degi_init_kernel() {
    int i = blockIdx.x * blockDim.x + threadIdx.x;
    if (i < N_NODES) g_degi[i] = 0;
}

__global__ void degi_count_kernel(const int* __restrict__ dst) {
    int e = blockIdx.x * blockDim.x + threadIdx.x;
    if (e < N_EDGES) {
        unsigned d = (unsigned)dst[e];
        if (d < N_NODES) atomicAdd(&g_degi[d], 1);
    }
}

// ---------------- device-wide exclusive scan (2 phases) ----------------
__global__ void scan_reduce_kernel() {
    __shared__ int sm[SCAN_BLK];
    const int tid = threadIdx.x;
    const int i = blockIdx.x * SCAN_BLK + tid;
    sm[tid] = (i < N_NODES) ? g_degi[i] : 0;
    __syncthreads();
#pragma unroll
    for (int off = SCAN_BLK / 2; off > 0; off >>= 1) {
        if (tid < off) sm[tid] += sm[tid + off];
        __syncthreads();
    }
    if (tid == 0) g_bsum[blockIdx.x] = sm[0];
}

__global__ void scan_write_kernel() {
    __shared__ int sb[SCAN_BLK];
    __shared__ int sm[SCAN_BLK];
    __shared__ int myorig;
    const int tid = threadIdx.x;
    const int bid = blockIdx.x;

    const int bv = (tid < SCAN_NBLK) ? g_bsum[tid] : 0;
    sb[tid] = bv;
    if (tid == bid) myorig = bv;

    const int i = bid * SCAN_BLK + tid;
    const int v = (i < N_NODES) ? g_degi[i] : 0;
    sm[tid] = v;
    __syncthreads();

#pragma unroll
    for (int off = 1; off < SCAN_BLK; off <<= 1) {
        int t1 = 0, t2 = 0;
        if (tid >= off) { t1 = sb[tid - off]; t2 = sm[tid - off]; }
        __syncthreads();
        if (tid >= off) { sb[tid] += t1; sm[tid] += t2; }
        __syncthreads();
    }

    if (bid == 0 && tid == 0) g_rowptr[N_NODES] = sb[SCAN_NBLK - 1];
    const int excl_b = sb[bid] - myorig;
    if (i < N_NODES) {
        const int pos = excl_b + sm[tid] - v;
        g_rowptr[i] = pos;
        g_cursor[i] = pos;
        g_dinv[i] = rsqrtf(1.0f + (float)v);
    }
}

__global__ void fill_kernel(const int* __restrict__ src,
                            const int* __restrict__ dst) {
    int e = blockIdx.x * blockDim.x + threadIdx.x;
    if (e < N_EDGES) {
        unsigned s = (unsigned)src[e];
        unsigned d = (unsigned)dst[e];
        if (s < N_NODES && d < N_NODES) {
            int pos = atomicAdd(&g_cursor[d], 1);
            g_col[pos] = (int)s;
        }
    }
}

// ---------------- tf32 / fp16 helpers ----------------
__device__ __forceinline__ uint32_t f2tf32(float x) {
    uint32_t y;
    asm("cvt.rna.tf32.f32 %0, %1;" : "=r"(y) : "f"(x));
    return y;
}

__device__ __forceinline__ void mma16n8k8(float* d, const uint32_t* a,
                                          const uint32_t* b) {
    asm volatile(
        "mma.sync.aligned.m16n8k8.row.col.f32.tf32.tf32.f32 "
        "{%0,%1,%2,%3}, {%4,%5,%6,%7}, {%8,%9}, {%0,%1,%2,%3};"
        : "+f"(d[0]), "+f"(d[1]), "+f"(d[2]), "+f"(d[3])
        : "r"(a[0]), "r"(a[1]), "r"(a[2]), "r"(a[3]), "r"(b[0]), "r"(b[1]));
}

__device__ __forceinline__ void cp_async16(void* dst, const void* src, bool pred) {
    const uint32_t d = (uint32_t)__cvta_generic_to_shared(dst);
    const int sz = pred ? 16 : 0;
    asm volatile("cp.async.ca.shared.global [%0], [%1], 16, %2;"
                 :: "r"(d), "l"(src), "r"(sz));
}

__device__ __forceinline__ float4 h4_to_f4(uint2 u) {
    const __half2 a = *reinterpret_cast<__half2*>(&u.x);
    const __half2 b = *reinterpret_cast<__half2*>(&u.y);
    const float2 fa = __half22float2(a);
    const float2 fb = __half22float2(b);
    return make_float4(fa.x, fa.y, fb.x, fb.y);
}

__device__ __forceinline__ uint2 f4_to_h4(float4 v) {
    __half2 a = __floats2half2_rn(v.x, v.y);
    __half2 b = __floats2half2_rn(v.z, v.w);
    uint2 u;
    u.x = *reinterpret_cast<uint32_t*>(&a);
    u.y = *reinterpret_cast<uint32_t*>(&b);
    return u;
}

// ---------------- GEMM1 (pipelined tf32): g_h1 = x @ W1 (fp16 out) ----------
__global__ void __launch_bounds__(128)
gemm1_kernel(const float* __restrict__ A, const float* __restrict__ W) {
    constexpr int K = IN_CH;
    constexpr int BK = 16;
    constexpr int NT = K / BK;
    __shared__ __align__(16) float As[2][64][28];
    __shared__ __align__(16) float Bs[2][16][136];

    const int tid = threadIdx.x;
    const int wid = tid >> 5;
    const int lane = tid & 31;
    const int g = lane >> 2;
    const int tg = lane & 3;
    const int m_w = (wid & 1) * 32;
    const int n_w = (wid >> 1) * 64;
    const int row0 = blockIdx.x * 64;

    float acc[2][8][4];
#pragma unroll
    for (int mt = 0; mt < 2; mt++)
#pragma unroll
        for (int nt = 0; nt < 8; nt++)
#pragma unroll
            for (int r = 0; r < 4; r++) acc[mt][nt][r] = 0.0f;

    const int ar0 = tid >> 2;
    const int ar1 = ar0 + 32;
    const int aq = (tid & 3) * 4;
    const bool ap0 = (row0 + ar0) < N_NODES;
    const bool ap1 = (row0 + ar1) < N_NODES;

#define ISSUE_TILE(t, b) do {                                                  \
    const int _k0 = (t) * BK;                                                  \
    cp_async16(&As[b][ar0][aq], &A[(size_t)(row0 + ar0) * K + _k0 + aq], ap0); \
    cp_async16(&As[b][ar1][aq], &A[(size_t)(row0 + ar1) * K + _k0 + aq], ap1); \
    _Pragma("unroll")                                                          \
    for (int _i = 0; _i < 4; _i++) {                                           \
        const int _f4 = _i * 128 + tid;                                        \
        const int _kk = _f4 >> 5;                                              \
        const int _c = (_f4 & 31) * 4;                                         \
        cp_async16(&Bs[b][_kk][_c], &W[(size_t)(_k0 + _kk) * HID + _c], true); \
    }                                                                          \
    asm volatile("cp.async.commit_group;" ::: "memory");                       \
} while (0)

    ISSUE_TILE(0, 0);

    for (int t = 0; t < NT; t++) {
        const int b = t & 1;
        if (t + 1 < NT) {
            ISSUE_TILE(t + 1, b ^ 1);
            asm volatile("cp.async.wait_group 1;" ::: "memory");
        } else {
            asm volatile("cp.async.wait_group 0;" ::: "memory");
        }
        __syncthreads();

#pragma unroll
        for (int s = 0; s < 2; s++) {
            uint32_t bf[8][2];
#pragma unroll
            for (int nt = 0; nt < 8; nt++) {
                bf[nt][0] = f2tf32(Bs[b][s * 8 + tg][n_w + nt * 8 + g]);
                bf[nt][1] = f2tf32(Bs[b][s * 8 + tg + 4][n_w + nt * 8 + g]);
            }
            uint32_t af[2][4];
#pragma unroll
            for (int mt = 0; mt < 2; mt++) {
                af[mt][0] = f2tf32(As[b][m_w + mt * 16 + g][s * 8 + tg]);
                af[mt][1] = f2tf32(As[b][m_w + mt * 16 + g + 8][s * 8 + tg]);
                af[mt][2] = f2tf32(As[b][m_w + mt * 16 + g][s * 8 + tg + 4]);
                af[mt][3] = f2tf32(As[b][m_w + mt * 16 + g + 8][s * 8 + tg + 4]);
            }
#pragma unroll
            for (int mt = 0; mt < 2; mt++)
#pragma unroll
                for (int nt = 0; nt < 8; nt++)
                    mma16n8k8(acc[mt][nt], af[mt], bf[nt]);
        }
        __syncthreads();
    }
#undef ISSUE_TILE

    // epilogue: fp16 output to g_h1
#pragma unroll
    for (int mt = 0; mt < 2; mt++) {
        const int r0 = row0 + m_w + mt * 16 + g;
#pragma unroll
        for (int nt = 0; nt < 8; nt++) {
            const int c0 = n_w + nt * 8 + 2 * tg;
            if (r0 < N_NODES) {
                __half2 v = __floats2half2_rn(acc[mt][nt][0], acc[mt][nt][1]);
                *reinterpret_cast<__half2*>(&g_h1[(size_t)r0 * HID + c0]) = v;
            }
            if (r0 + 8 < N_NODES) {
                __half2 v = __floats2half2_rn(acc[mt][nt][2], acc[mt][nt][3]);
                *reinterpret_cast<__half2*>(&g_h1[(size_t)(r0 + 8) * HID + c0]) = v;
            }
        }
    }
}

// ---------------- CSR gather (fp16 rows, fp32 accumulation) ------------------
// MODE 0: g_h2 = relu(A_hat*g_h1 + b);  MODE 1: g_agg2 = A_hat*g_h2
template <int MODE>
__global__ void __launch_bounds__(256)
gather_kernel(const float* __restrict__ bias) {
    const __half* h = (MODE == 0) ? g_h1 : g_h2;
    __half* o = (MODE == 0) ? g_h2 : g_agg2;

    const int n = blockIdx.x * 8 + (threadIdx.x >> 5);
    const int lane = threadIdx.x & 31;
    if (n >= N_NODES) return;

    const float dn = g_dinv[n];
    const int beg = g_rowptr[n];
    const int end = g_rowptr[n + 1];

    float4 acc = h4_to_f4(reinterpret_cast<const uint2*>(h + (size_t)n * HID)[lane]);
    const float s2 = dn * dn;
    acc.x *= s2; acc.y *= s2; acc.z *= s2; acc.w *= s2;

    int e = beg;
    for (; e + 4 <= end; e += 4) {
        const int s0 = g_col[e];
        const int s1 = g_col[e + 1];
        const int s2i = g_col[e + 2];
        const int s3 = g_col[e + 3];
        const float w0 = dn * g_dinv[s0];
        const float w1 = dn * g_dinv[s1];
        const float w2 = dn * g_dinv[s2i];
        const float w3 = dn * g_dinv[s3];
        const float4 v0 = h4_to_f4(reinterpret_cast<const uint2*>(h + (size_t)s0 * HID)[lane]);
        const float4 v1 = h4_to_f4(reinterpret_cast<const uint2*>(h + (size_t)s1 * HID)[lane]);
        const float4 v2 = h4_to_f4(reinterpret_cast<const uint2*>(h + (size_t)s2i * HID)[lane]);
        const float4 v3 = h4_to_f4(reinterpret_cast<const uint2*>(h + (size_t)s3 * HID)[lane]);
        acc.x = fmaf(w0, v0.x, acc.x); acc.y = fmaf(w0, v0.y, acc.y);
        acc.z = fmaf(w0, v0.z, acc.z); acc.w = fmaf(w0, v0.w, acc.w);
        acc.x = fmaf(w1, v1.x, acc.x); acc.y = fmaf(w1, v1.y, acc.y);
        acc.z = fmaf(w1, v1.z, acc.z); acc.w = fmaf(w1, v1.w, acc.w);
        acc.x = fmaf(w2, v2.x, acc.x); acc.y = fmaf(w2, v2.y, acc.y);
        acc.z = fmaf(w2, v2.z, acc.z); acc.w = fmaf(w2, v2.w, acc.w);
        acc.x = fmaf(w3, v3.x, acc.x); acc.y = fmaf(w3, v3.y, acc.y);
        acc.z = fmaf(w3, v3.z, acc.z); acc.w = fmaf(w3, v3.w, acc.w);
    }
    for (; e < end; e++) {
        const int s0 = g_col[e];
        const float w0 = dn * g_dinv[s0];
        const float4 v0 = h4_to_f4(reinterpret_cast<const uint2*>(h + (size_t)s0 * HID)[lane]);
        acc.x = fmaf(w0, v0.x, acc.x); acc.y = fmaf(w0, v0.y, acc.y);
        acc.z = fmaf(w0, v0.z, acc.z); acc.w = fmaf(w0, v0.w, acc.w);
    }

    if (MODE == 0) {
        const float4 b = reinterpret_cast<const float4*>(bias)[lane];
        acc.x = fmaxf(acc.x + b.x, 0.0f);
        acc.y = fmaxf(acc.y + b.y, 0.0f);
        acc.z = fmaxf(acc.z + b.z, 0.0f);
        acc.w = fmaxf(acc.w + b.w, 0.0f);
    }
    reinterpret_cast<uint2*>(o + (size_t)n * HID)[lane] = f4_to_h4(acc);
}

// ---------------- GEMM2 (tf32): out = g_agg2 @ W2 + b2 (fp16 in, fp32 out) --
__global__ void __launch_bounds__(128)
gemm2_kernel(float* __restrict__ C, const float* __restrict__ W,
             const float* __restrict__ bias) {
    __shared__ uint32_t As[64][20];   // tf32 bits, stride 20 (conflict-free)
    __shared__ uint32_t Bs[16][136];

    const int tid = threadIdx.x;
    const int wid = tid >> 5;
    const int lane = tid & 31;
    const int g = lane >> 2;
    const int tg = lane & 3;
    const int m_w = (wid & 1) * 32;
    const int n_w = (wid >> 1) * 64;
    const int row0 = blockIdx.x * 64;

    float acc[2][8][4];
#pragma unroll
    for (int mt = 0; mt < 2; mt++)
#pragma unroll
        for (int nt = 0; nt < 8; nt++)
#pragma unroll
            for (int r = 0; r < 4; r++) acc[mt][nt][r] = 0.0f;

    for (int k0 = 0; k0 < HID; k0 += 16) {
        // A tile: 64 rows x 16 halves (32B/row); each thread: 8 halves
        {
            const int r = tid >> 1;
            const int h8 = (tid & 1) * 8;
            const int grow = row0 + r;
            uint4 u = make_uint4(0, 0, 0, 0);
            if (grow < N_NODES)
                u = *reinterpret_cast<const uint4*>(&g_agg2[(size_t)grow * HID + k0 + h8]);
            const __half2* hp = reinterpret_cast<const __half2*>(&u);
#pragma unroll
            for (int j = 0; j < 4; j++) {
                const float2 f = __half22float2(hp[j]);
                As[r][h8 + j * 2 + 0] = f2tf32(f.x);
                As[r][h8 + j * 2 + 1] = f2tf32(f.y);
            }
        }
        // B tile: 16 k x 128 n fp32
#pragma unroll
        for (int i = 0; i < 4; i++) {
            const int f4 = i * 128 + tid;
            const int kk = f4 >> 5;
            const int c = (f4 & 31) * 4;
            const float4 v = *reinterpret_cast<const float4*>(&W[(size_t)(k0 + kk) * HID + c]);
            Bs[kk][c + 0] = f2tf32(v.x);
            Bs[kk][c + 1] = f2tf32(v.y);
            Bs[kk][c + 2] = f2tf32(v.z);
            Bs[kk][c + 3] = f2tf32(v.w);
        }
        __syncthreads();

#pragma unroll
        for (int s = 0; s < 2; s++) {
            uint32_t bf[8][2];
#pragma unroll
            for (int nt = 0; nt < 8; nt++) {
                bf[nt][0] = Bs[s * 8 + tg][n_w + nt * 8 + g];
                bf[nt][1] = Bs[s * 8 + tg + 4][n_w + nt * 8 + g];
            }
            uint32_t af[2][4];
#pragma unroll
            for (int mt = 0; mt < 2; mt++) {
                af[mt][0] = As[m_w + mt * 16 + g][s * 8 + tg];
                af[mt][1] = As[m_w + mt * 16 + g + 8][s * 8 + tg];
                af[mt][2] = As[m_w + mt * 16 + g][s * 8 + tg + 4];
                af[mt][3] = As[m_w + mt * 16 + g + 8][s * 8 + tg + 4];
            }
#pragma unroll
            for (int mt = 0; mt < 2; mt++)
#pragma unroll
                for (int nt = 0; nt < 8; nt++)
                    mma16n8k8(acc[mt][nt], af[mt], bf[nt]);
        }
        __syncthreads();
    }

#pragma unroll
    for (int mt = 0; mt < 2; mt++) {
        const int r0 = row0 + m_w + mt * 16 + g;
#pragma unroll
        for (int nt = 0; nt < 8; nt++) {
            const int c0 = n_w + nt * 8 + 2 * tg;
            const float b0 = bias[c0];
            const float b1 = bias[c0 + 1];
            if (r0 < N_NODES) {
                float2 v = make_float2(acc[mt][nt][0] + b0, acc[mt][nt][1] + b1);
                *reinterpret_cast<float2*>(&C[(size_t)r0 * HID + c0]) = v;
            }
            if (r0 + 8 < N_NODES) {
                float2 v = make_float2(acc[mt][nt][2] + b0, acc[mt][nt][3] + b1);
                *reinterpret_cast<float2*>(&C[(size_t)(r0 + 8) * HID + c0]) = v;
            }
        }
    }
}

extern "C" void kernel_launch(void* const* d_in, const int* in_sizes, int n_in,
                              void* d_out, int out_size) {
    const float* x   = (const float*)d_in[0];
    const int* ei    = (const int*)d_in[1];   // int64 marshaled as int32
    const float* W1  = (const float*)d_in[2];
    const float* b1  = (const float*)d_in[3];
    const float* W2  = (const float*)d_in[4];
    const float* b2  = (const float*)d_in[5];
    float* out       = (float*)d_out;

    const int* src = ei;            // edge_index[0]
    const int* dst = ei + N_EDGES;  // edge_index[1]

    const int nb = (N_NODES + 255) / 256;
    const int ebk = (N_EDGES + 255) / 256;
    const int gemm_blocks = (N_NODES + 63) / 64;
    const int gather_blocks = (N_NODES + 7) / 8;

    // fork: CSR build on side stream, GEMM1 on the main (legacy) stream
    cudaStream_t s1;
    cudaStreamCreateWithFlags(&s1, cudaStreamNonBlocking);
    cudaEvent_t ev_fork, ev_join;
    cudaEventCreateWithFlags(&ev_fork, cudaEventDisableTiming);
    cudaEventCreateWithFlags(&ev_join, cudaEventDisableTiming);

    cudaEventRecord(ev_fork, 0);
    cudaStreamWaitEvent(s1, ev_fork, 0);

    // CSR branch (s1)
    degi_init_kernel<<<nb, 256, 0, s1>>>();
    degi_count_kernel<<<ebk, 256, 0, s1>>>(dst);
    scan_reduce_kernel<<<SCAN_NBLK, SCAN_BLK, 0, s1>>>();
    scan_write_kernel<<<SCAN_NBLK, SCAN_BLK, 0, s1>>>();
    fill_kernel<<<ebk, 256, 0, s1>>>(src, dst);
    cudaEventRecord(ev_join, s1);

    // GEMM1 branch (legacy stream, concurrent): g_h1 = x@W1 (fp16)
    gemm1_kernel<<<gemm_blocks, 128>>>(x, W1);

    // join
    cudaStreamWaitEvent(0, ev_join, 0);

    // g_h2 = relu(A_hat*g_h1 + b1)
    gather_kernel<0><<<gather_blocks, 256>>>(b1);
    // g_agg2 = A_hat*g_h2 ; out = g_agg2@W2 + b2
    gather_kernel<1><<<gather_blocks, 256>>>(nullptr);
    gemm2_kernel<<<gemm_blocks, 128>>>(out, W2, b2);
}

// round 15
// speedup vs baseline: 1.0059x; 1.0059x over previous
#include <cuda_runtime.h>
#include <cuda_fp16.h>
#include <stdint.h>

#define N_NODES 50000
#define N_EDGES 800000
#define IN_CH 384
#define HID 128

#define SCAN_BLK 256
#define SCAN_NBLK ((N_NODES + SCAN_BLK - 1) / SCAN_BLK)   // 196

// ---------------- scratch (device-code-only references!) ----------------
__device__ __align__(256) __half g_h1[N_NODES * HID];    // GEMM1 out (fp16)
__device__ __align__(256) __half g_h2[N_NODES * HID];    // layer-1 out (fp16)
__device__ __align__(256) __half g_agg2[N_NODES * HID];  // A_hat*h2 (fp16)
__device__ float g_dinv[N_NODES];
__device__ int g_degi[N_NODES];
__device__ int g_rowptr[N_NODES + 1];
__device__ int g_cursor[N_NODES];
__device__ int2 g_meta[N_EDGES];    // (src, bits(dinv[src])) per edge, CSR order
__device__ int g_bsum[SCAN_NBLK];

// ---------------- degree ----------------
__global__ void degi_init_kernel() {
    int i = blockIdx.x * blockDim.x + threadIdx.x;
    if (i < N_NODES) g_degi[i] = 0;
}

__global__ void degi_count_kernel(const int* __restrict__ dst) {
    int e = blockIdx.x * blockDim.x + threadIdx.x;
    if (e < N_EDGES) {
        unsigned d = (unsigned)dst[e];
        if (d < N_NODES) atomicAdd(&g_degi[d], 1);
    }
}

// ---------------- device-wide exclusive scan (2 phases) ----------------
__global__ void scan_reduce_kernel() {
    __shared__ int sm[SCAN_BLK];
    const int tid = threadIdx.x;
    const int i = blockIdx.x * SCAN_BLK + tid;
    sm[tid] = (i < N_NODES) ? g_degi[i] : 0;
    __syncthreads();
#pragma unroll
    for (int off = SCAN_BLK / 2; off > 0; off >>= 1) {
        if (tid < off) sm[tid] += sm[tid + off];
        __syncthreads();
    }
    if (tid == 0) g_bsum[blockIdx.x] = sm[0];
}

__global__ void scan_write_kernel() {
    __shared__ int sb[SCAN_BLK];
    __shared__ int sm[SCAN_BLK];
    __shared__ int myorig;
    const int tid = threadIdx.x;
    const int bid = blockIdx.x;

    const int bv = (tid < SCAN_NBLK) ? g_bsum[tid] : 0;
    sb[tid] = bv;
    if (tid == bid) myorig = bv;

    const int i = bid * SCAN_BLK + tid;
    const int v = (i < N_NODES) ? g_degi[i] : 0;
    sm[tid] = v;
    __syncthreads();

#pragma unroll
    for (int off = 1; off < SCAN_BLK; off <<= 1) {
        int t1 = 0, t2 = 0;
        if (tid >= off) { t1 = sb[tid - off]; t2 = sm[tid - off]; }
        __syncthreads();
        if (tid >= off) { sb[tid] += t1; sm[tid] += t2; }
        __syncthreads();
    }

    if (bid == 0 && tid == 0) g_rowptr[N_NODES] = sb[SCAN_NBLK - 1];
    const int excl_b = sb[bid] - myorig;
    if (i < N_NODES) {
        const int pos = excl_b + sm[tid] - v;
        g_rowptr[i] = pos;
        g_cursor[i] = pos;
        g_dinv[i] = rsqrtf(1.0f + (float)v);
    }
}

// fill CSR with packed (src, dinv[src]) metadata
__global__ void fill_kernel(const int* __restrict__ src,
                            const int* __restrict__ dst) {
    int e = blockIdx.x * blockDim.x + threadIdx.x;
    if (e < N_EDGES) {
        unsigned s = (unsigned)src[e];
        unsigned d = (unsigned)dst[e];
        if (s < N_NODES && d < N_NODES) {
            int pos = atomicAdd(&g_cursor[d], 1);
            g_meta[pos] = make_int2((int)s, __float_as_int(g_dinv[s]));
        }
    }
}

// ---------------- tf32 / fp16 helpers ----------------
__device__ __forceinline__ uint32_t f2tf32(float x) {
    uint32_t y;
    asm("cvt.rna.tf32.f32 %0, %1;" : "=r"(y) : "f"(x));
    return y;
}

__device__ __forceinline__ void mma16n8k8(float* d, const uint32_t* a,
                                          const uint32_t* b) {
    asm volatile(
        "mma.sync.aligned.m16n8k8.row.col.f32.tf32.tf32.f32 "
        "{%0,%1,%2,%3}, {%4,%5,%6,%7}, {%8,%9}, {%0,%1,%2,%3};"
        : "+f"(d[0]), "+f"(d[1]), "+f"(d[2]), "+f"(d[3])
        : "r"(a[0]), "r"(a[1]), "r"(a[2]), "r"(a[3]), "r"(b[0]), "r"(b[1]));
}

__device__ __forceinline__ void cp_async16(void* dst, const void* src, bool pred) {
    const uint32_t d = (uint32_t)__cvta_generic_to_shared(dst);
    const int sz = pred ? 16 : 0;
    asm volatile("cp.async.ca.shared.global [%0], [%1], 16, %2;"
                 :: "r"(d), "l"(src), "r"(sz));
}

__device__ __forceinline__ float4 h4_to_f4(uint2 u) {
    const __half2 a = *reinterpret_cast<__half2*>(&u.x);
    const __half2 b = *reinterpret_cast<__half2*>(&u.y);
    const float2 fa = __half22float2(a);
    const float2 fb = __half22float2(b);
    return make_float4(fa.x, fa.y, fb.x, fb.y);
}

__device__ __forceinline__ uint2 f4_to_h4(float4 v) {
    __half2 a = __floats2half2_rn(v.x, v.y);
    __half2 b = __floats2half2_rn(v.z, v.w);
    uint2 u;
    u.x = *reinterpret_cast<uint32_t*>(&a);
    u.y = *reinterpret_cast<uint32_t*>(&b);
    return u;
}

// ---------------- GEMM1 (pipelined tf32): g_h1 = x @ W1 (fp16 out) ----------
__global__ void __launch_bounds__(128)
gemm1_kernel(const float* __restrict__ A, const float* __restrict__ W) {
    constexpr int K = IN_CH;
    constexpr int BK = 16;
    constexpr int NT = K / BK;
    __shared__ __align__(16) float As[2][64][28];
    __shared__ __align__(16) float Bs[2][16][136];

    const int tid = threadIdx.x;
    const int wid = tid >> 5;
    const int lane = tid & 31;
    const int g = lane >> 2;
    const int tg = lane & 3;
    const int m_w = (wid & 1) * 32;
    const int n_w = (wid >> 1) * 64;
    const int row0 = blockIdx.x * 64;

    float acc[2][8][4];
#pragma unroll
    for (int mt = 0; mt < 2; mt++)
#pragma unroll
        for (int nt = 0; nt < 8; nt++)
#pragma unroll
            for (int r = 0; r < 4; r++) acc[mt][nt][r] = 0.0f;

    const int ar0 = tid >> 2;
    const int ar1 = ar0 + 32;
    const int aq = (tid & 3) * 4;
    const bool ap0 = (row0 + ar0) < N_NODES;
    const bool ap1 = (row0 + ar1) < N_NODES;

#define ISSUE_TILE(t, b) do {                                                  \
    const int _k0 = (t) * BK;                                                  \
    cp_async16(&As[b][ar0][aq], &A[(size_t)(row0 + ar0) * K + _k0 + aq], ap0); \
    cp_async16(&As[b][ar1][aq], &A[(size_t)(row0 + ar1) * K + _k0 + aq], ap1); \
    _Pragma("unroll")                                                          \
    for (int _i = 0; _i < 4; _i++) {                                           \
        const int _f4 = _i * 128 + tid;                                        \
        const int _kk = _f4 >> 5;                                              \
        const int _c = (_f4 & 31) * 4;                                         \
        cp_async16(&Bs[b][_kk][_c], &W[(size_t)(_k0 + _kk) * HID + _c], true); \
    }                                                                          \
    asm volatile("cp.async.commit_group;" ::: "memory");                       \
} while (0)

    ISSUE_TILE(0, 0);

    for (int t = 0; t < NT; t++) {
        const int b = t & 1;
        if (t + 1 < NT) {
            ISSUE_TILE(t + 1, b ^ 1);
            asm volatile("cp.async.wait_group 1;" ::: "memory");
        } else {
            asm volatile("cp.async.wait_group 0;" ::: "memory");
        }
        __syncthreads();

#pragma unroll
        for (int s = 0; s < 2; s++) {
            uint32_t bf[8][2];
#pragma unroll
            for (int nt = 0; nt < 8; nt++) {
                bf[nt][0] = f2tf32(Bs[b][s * 8 + tg][n_w + nt * 8 + g]);
                bf[nt][1] = f2tf32(Bs[b][s * 8 + tg + 4][n_w + nt * 8 + g]);
            }
            uint32_t af[2][4];
#pragma unroll
            for (int mt = 0; mt < 2; mt++) {
                af[mt][0] = f2tf32(As[b][m_w + mt * 16 + g][s * 8 + tg]);
                af[mt][1] = f2tf32(As[b][m_w + mt * 16 + g + 8][s * 8 + tg]);
                af[mt][2] = f2tf32(As[b][m_w + mt * 16 + g][s * 8 + tg + 4]);
                af[mt][3] = f2tf32(As[b][m_w + mt * 16 + g + 8][s * 8 + tg + 4]);
            }
#pragma unroll
            for (int mt = 0; mt < 2; mt++)
#pragma unroll
                for (int nt = 0; nt < 8; nt++)
                    mma16n8k8(acc[mt][nt], af[mt], bf[nt]);
        }
        __syncthreads();
    }
#undef ISSUE_TILE

#pragma unroll
    for (int mt = 0; mt < 2; mt++) {
        const int r0 = row0 + m_w + mt * 16 + g;
#pragma unroll
        for (int nt = 0; nt < 8; nt++) {
            const int c0 = n_w + nt * 8 + 2 * tg;
            if (r0 < N_NODES) {
                __half2 v = __floats2half2_rn(acc[mt][nt][0], acc[mt][nt][1]);
                *reinterpret_cast<__half2*>(&g_h1[(size_t)r0 * HID + c0]) = v;
            }
            if (r0 + 8 < N_NODES) {
                __half2 v = __floats2half2_rn(acc[mt][nt][2], acc[mt][nt][3]);
                *reinterpret_cast<__half2*>(&g_h1[(size_t)(r0 + 8) * HID + c0]) = v;
            }
        }
    }
}

// ---------------- CSR gather (packed meta, 8-edge unroll) ---------------------
// MODE 0: g_h2 = relu(A_hat*g_h1 + b);  MODE 1: g_agg2 = A_hat*g_h2
template <int MODE>
__global__ void __launch_bounds__(256)
gather_kernel(const float* __restrict__ bias) {
    const __half* h = (MODE == 0) ? g_h1 : g_h2;
    __half* o = (MODE == 0) ? g_h2 : g_agg2;

    const int n = blockIdx.x * 8 + (threadIdx.x >> 5);
    const int lane = threadIdx.x & 31;
    if (n >= N_NODES) return;

    const float dn = g_dinv[n];
    const int beg = g_rowptr[n];
    const int cnt = g_rowptr[n + 1] - beg;
    const int2* mp = g_meta + beg;

    float4 acc = h4_to_f4(__ldg(reinterpret_cast<const uint2*>(h + (size_t)n * HID) + lane));
    const float s2 = dn * dn;
    acc.x *= s2; acc.y *= s2; acc.z *= s2; acc.w *= s2;

    int e = 0;
    for (; e + 8 <= cnt; e += 8) {
        int2 m[8];
#pragma unroll
        for (int j = 0; j < 8; j++) m[j] = __ldg(&mp[e + j]);
        uint2 u[8];
#pragma unroll
        for (int j = 0; j < 8; j++)
            u[j] = __ldg(reinterpret_cast<const uint2*>(h + (size_t)m[j].x * HID) + lane);
#pragma unroll
        for (int j = 0; j < 8; j++) {
            const float w = dn * __int_as_float(m[j].y);
            const float4 v = h4_to_f4(u[j]);
            acc.x = fmaf(w, v.x, acc.x);
            acc.y = fmaf(w, v.y, acc.y);
            acc.z = fmaf(w, v.z, acc.z);
            acc.w = fmaf(w, v.w, acc.w);
        }
    }
    for (; e < cnt; e++) {
        const int2 m = __ldg(&mp[e]);
        const float w = dn * __int_as_float(m.y);
        const float4 v = h4_to_f4(
            __ldg(reinterpret_cast<const uint2*>(h + (size_t)m.x * HID) + lane));
        acc.x = fmaf(w, v.x, acc.x);
        acc.y = fmaf(w, v.y, acc.y);
        acc.z = fmaf(w, v.z, acc.z);
        acc.w = fmaf(w, v.w, acc.w);
    }

    if (MODE == 0) {
        const float4 b = reinterpret_cast<const float4*>(bias)[lane];
        acc.x = fmaxf(acc.x + b.x, 0.0f);
        acc.y = fmaxf(acc.y + b.y, 0.0f);
        acc.z = fmaxf(acc.z + b.z, 0.0f);
        acc.w = fmaxf(acc.w + b.w, 0.0f);
    }
    reinterpret_cast<uint2*>(o + (size_t)n * HID)[lane] = f4_to_h4(acc);
}

// ---------------- GEMM2 (tf32): out = g_agg2 @ W2 + b2 (fp16 in, fp32 out) --
__global__ void __launch_bounds__(128)
gemm2_kernel(float* __restrict__ C, const float* __restrict__ W,
             const float* __restrict__ bias) {
    __shared__ uint32_t As[64][20];
    __shared__ uint32_t Bs[16][136];

    const int tid = threadIdx.x;
    const int wid = tid >> 5;
    const int lane = tid & 31;
    const int g = lane >> 2;
    const int tg = lane & 3;
    const int m_w = (wid & 1) * 32;
    const int n_w = (wid >> 1) * 64;
    const int row0 = blockIdx.x * 64;

    float acc[2][8][4];
#pragma unroll
    for (int mt = 0; mt < 2; mt++)
#pragma unroll
        for (int nt = 0; nt < 8; nt++)
#pragma unroll
            for (int r = 0; r < 4; r++) acc[mt][nt][r] = 0.0f;

    for (int k0 = 0; k0 < HID; k0 += 16) {
        {
            const int r = tid >> 1;
            const int h8 = (tid & 1) * 8;
            const int grow = row0 + r;
            uint4 u = make_uint4(0, 0, 0, 0);
            if (grow < N_NODES)
                u = *reinterpret_cast<const uint4*>(&g_agg2[(size_t)grow * HID + k0 + h8]);
            const __half2* hp = reinterpret_cast<const __half2*>(&u);
#pragma unroll
            for (int j = 0; j < 4; j++) {
                const float2 f = __half22float2(hp[j]);
                As[r][h8 + j * 2 + 0] = f2tf32(f.x);
                As[r][h8 + j * 2 + 1] = f2tf32(f.y);
            }
        }
#pragma unroll
        for (int i = 0; i < 4; i++) {
            const int f4 = i * 128 + tid;
            const int kk = f4 >> 5;
            const int c = (f4 & 31) * 4;
            const float4 v = *reinterpret_cast<const float4*>(&W[(size_t)(k0 + kk) * HID + c]);
            Bs[kk][c + 0] = f2tf32(v.x);
            Bs[kk][c + 1] = f2tf32(v.y);
            Bs[kk][c + 2] = f2tf32(v.z);
            Bs[kk][c + 3] = f2tf32(v.w);
        }
        __syncthreads();

#pragma unroll
        for (int s = 0; s < 2; s++) {
            uint32_t bf[8][2];
#pragma unroll
            for (int nt = 0; nt < 8; nt++) {
                bf[nt][0] = Bs[s * 8 + tg][n_w + nt * 8 + g];
                bf[nt][1] = Bs[s * 8 + tg + 4][n_w + nt * 8 + g];
            }
            uint32_t af[2][4];
#pragma unroll
            for (int mt = 0; mt < 2; mt++) {
                af[mt][0] = As[m_w + mt * 16 + g][s * 8 + tg];
                af[mt][1] = As[m_w + mt * 16 + g + 8][s * 8 + tg];
                af[mt][2] = As[m_w + mt * 16 + g][s * 8 + tg + 4];
                af[mt][3] = As[m_w + mt * 16 + g + 8][s * 8 + tg + 4];
            }
#pragma unroll
            for (int mt = 0; mt < 2; mt++)
#pragma unroll
                for (int nt = 0; nt < 8; nt++)
                    mma16n8k8(acc[mt][nt], af[mt], bf[nt]);
        }
        __syncthreads();
    }

#pragma unroll
    for (int mt = 0; mt < 2; mt++) {
        const int r0 = row0 + m_w + mt * 16 + g;
#pragma unroll
        for (int nt = 0; nt < 8; nt++) {
            const int c0 = n_w + nt * 8 + 2 * tg;
            const float b0 = bias[c0];
            const float b1 = bias[c0 + 1];
            if (r0 < N_NODES) {
                float2 v = make_float2(acc[mt][nt][0] + b0, acc[mt][nt][1] + b1);
                *reinterpret_cast<float2*>(&C[(size_t)r0 * HID + c0]) = v;
            }
            if (r0 + 8 < N_NODES) {
                float2 v = make_float2(acc[mt][nt][2] + b0, acc[mt][nt][3] + b1);
                *reinterpret_cast<float2*>(&C[(size_t)(r0 + 8) * HID + c0]) = v;
            }
        }
    }
}

extern "C" void kernel_launch(void* const* d_in, const int* in_sizes, int n_in,
                              void* d_out, int out_size) {
    const float* x   = (const float*)d_in[0];
    const int* ei    = (const int*)d_in[1];   // int64 marshaled as int32
    const float* W1  = (const float*)d_in[2];
    const float* b1  = (const float*)d_in[3];
    const float* W2  = (const float*)d_in[4];
    const float* b2  = (const float*)d_in[5];
    float* out       = (float*)d_out;

    const int* src = ei;            // edge_index[0]
    const int* dst = ei + N_EDGES;  // edge_index[1]

    const int nb = (N_NODES + 255) / 256;
    const int ebk = (N_EDGES + 255) / 256;
    const int gemm_blocks = (N_NODES + 63) / 64;
    const int gather_blocks = (N_NODES + 7) / 8;

    // fork: CSR build on side stream, GEMM1 on the main (legacy) stream
    cudaStream_t s1;
    cudaStreamCreateWithFlags(&s1, cudaStreamNonBlocking);
    cudaEvent_t ev_fork, ev_join;
    cudaEventCreateWithFlags(&ev_fork, cudaEventDisableTiming);
    cudaEventCreateWithFlags(&ev_join, cudaEventDisableTiming);

    cudaEventRecord(ev_fork, 0);
    cudaStreamWaitEvent(s1, ev_fork, 0);

    // CSR branch (s1)
    degi_init_kernel<<<nb, 256, 0, s1>>>();
    degi_count_kernel<<<ebk, 256, 0, s1>>>(dst);
    scan_reduce_kernel<<<SCAN_NBLK, SCAN_BLK, 0, s1>>>();
    scan_write_kernel<<<SCAN_NBLK, SCAN_BLK, 0, s1>>>();
    fill_kernel<<<ebk, 256, 0, s1>>>(src, dst);
    cudaEventRecord(ev_join, s1);

    // GEMM1 branch (legacy stream, concurrent): g_h1 = x@W1 (fp16)
    gemm1_kernel<<<gemm_blocks, 128>>>(x, W1);

    // join
    cudaStreamWaitEvent(0, ev_join, 0);

    // g_h2 = relu(A_hat*g_h1 + b1)
    gather_kernel<0><<<gather_blocks, 256>>>(b1);
    // g_agg2 = A_hat*g_h2 ; out = g_agg2@W2 + b2
    gather_kernel<1><<<gather_blocks, 256>>>(nullptr);
    gemm2_kernel<<<gemm_blocks, 128>>>(out, W2, b2);
}